// round 17
// baseline (speedup 1.0000x reference)
#include <cuda_runtime.h>
#include <math.h>
#include <stdint.h>

// Problem constants
#define B_  4
#define N_  2048
#define D_  1024
#define E_  16
#define C_  256
#define BNEC_ (4LL * 2048 * 16 * 256)   // 33,554,432 elements per output tensor
#define FLT_MIN_NORMAL 1.17549435082228750797e-38f  // 2^-126

#define NLOG  1024               // logits blocks (2 halves x 512, 2 tok/warp)
#define NTOPK 64
#define NK1   (NLOG + NTOPK)
#define NWRITE 4096
#define HALF_OFF (B_ * E_ * N_)

// Partial logits [half][b][e][n] (raw dots; topk applies /exp(temp))
__device__ float g_plog[2 * B_ * E_ * N_];
// Per-(b,e,token) result table: low32 = slot c (or 0xFFFFFFFF), high32 = valbits.
// Fully rewritten every launch (complete coverage), so no reset needed.
__device__ unsigned long long g_tab[B_ * E_ * N_];
// Logits-completion counter; reset by last topk block for graph determinism.
__device__ volatile int g_log_done;
__device__ int g_reset_cnt;

// ---------------------------------------------------------------------------
// Kernel 1: logits (1024 blocks, R16-verbatim math) + 64 topk tail blocks.
// Topk spins on g_log_done (only 64 spinners; producers never wait), runs the
// R14-proven select-then-rank, and writes g_tab instead of touching `out`.
// No fill in this kernel => the sync cannot tax the store roofline.
// ---------------------------------------------------------------------------
__global__ __launch_bounds__(256, 4) void logits_topk_kernel(
        const float* __restrict__ key,
        const float* __restrict__ query,
        const float* __restrict__ temp) {
    __shared__ __align__(16) unsigned char smbuf[33920];
    const int bx  = blockIdx.x;
    const int tid = threadIdx.x;
    const int lane = tid & 31;
    const int warp = tid >> 5;

    if (bx < NLOG) {
        // ================= logits role (R16 verbatim) =================
        float* sq = (float*)smbuf;                       // 32 KB
        float (*tile)[17] = (float(*)[17])(smbuf + 32768);
        const int lid_blk = bx;                          // 0..1023
        const int half = lid_blk >> 9;
        const int tok0 = ((lid_blk & 511) * 8 + warp) * 2;

        const float4* kp[2];
        #pragma unroll
        for (int t = 0; t < 2; ++t)
            kp[t] = reinterpret_cast<const float4*>(
                        key + (long long)(tok0 + t) * D_ + half * 512);
        float4 kv[2], kvn[2];
        #pragma unroll
        for (int t = 0; t < 2; ++t) kv[t] = kp[t][lane];

        for (int i = tid; i < E_ * 512; i += 256) {
            int e = i >> 9, j = i & 511;
            sq[i] = query[e * D_ + half * 512 + j];
        }
        __syncthreads();

        float acc[2][E_];
        #pragma unroll
        for (int t = 0; t < 2; t++)
            #pragma unroll
            for (int e = 0; e < E_; e++) acc[t][e] = 0.f;

        const float4* sq4 = reinterpret_cast<const float4*>(sq);
        #pragma unroll
        for (int i = 0; i < 4; ++i) {
            if (i < 3) {
                int dvn = lane + 32 * (i + 1);
                #pragma unroll
                for (int t = 0; t < 2; ++t) kvn[t] = kp[t][dvn];
            }
            int dv = lane + 32 * i;
            #pragma unroll
            for (int e = 0; e < E_; ++e) {
                float4 q = sq4[e * 128 + dv];
                #pragma unroll
                for (int t = 0; t < 2; ++t) {
                    acc[t][e] += kv[t].x * q.x;
                    acc[t][e] += kv[t].y * q.y;
                    acc[t][e] += kv[t].z * q.z;
                    acc[t][e] += kv[t].w * q.w;
                }
            }
            #pragma unroll
            for (int t = 0; t < 2; ++t) kv[t] = kvn[t];
        }

        #pragma unroll
        for (int t = 0; t < 2; ++t) {
            #pragma unroll
            for (int e = 0; e < E_; ++e) {
                float v = acc[t][e];
                #pragma unroll
                for (int off = 16; off > 0; off >>= 1)
                    v += __shfl_xor_sync(0xffffffffu, v, off);
                if (lane == 0) tile[e][warp * 2 + t] = v;
            }
        }
        __syncthreads();

        {
            int base = (lid_blk & 511) * 16;
            int b = base >> 11, n0 = base & (N_ - 1);
            int e = tid >> 4, tk = tid & 15;
            g_plog[half * HALF_OFF + (b * E_ + e) * N_ + n0 + tk] = tile[e][tk];
        }
        __threadfence();
        __syncthreads();
        if (tid == 0) atomicAdd((int*)&g_log_done, 1);
        return;
    }

    // ================= topk role (R14-proven; 256 thr, 8 tokens/thread) ====
    unsigned long long* sk = (unsigned long long*)smbuf;   // 2 KB
    float* redf = (float*)(smbuf + 2048);
    int*   wcnt = (int*)(smbuf + 2176);
    int*   wbase= (int*)(smbuf + 2240);
    int*   mPtr = (int*)(smbuf + 2304);
    float* af   = (float*)(smbuf + 4096);                  // 8 KB fallback

    const int be = bx - NLOG;             // 0..63 == b*16+e
    unsigned long long* tabrow = g_tab + (long long)be * N_;

    if (tid == 0) { while (g_log_done < NLOG) __nanosleep(64); }
    __syncthreads();
    __threadfence();

    const float et = expf(temp[0]);
    const float4* pA = (const float4*)(g_plog + (long long)be * N_);
    const float4* pB = (const float4*)(g_plog + HALF_OFF + (long long)be * N_);
    float xv[8];
    {
        float4 a0 = pA[2 * tid], a1 = pA[2 * tid + 1];
        float4 b0 = pB[2 * tid], b1 = pB[2 * tid + 1];
        xv[0] = (a0.x + b0.x) / et;  xv[1] = (a0.y + b0.y) / et;
        xv[2] = (a0.z + b0.z) / et;  xv[3] = (a0.w + b0.w) / et;
        xv[4] = (a1.x + b1.x) / et;  xv[5] = (a1.y + b1.y) / et;
        xv[6] = (a1.z + b1.z) / et;  xv[7] = (a1.w + b1.w) / et;
    }

    // ---- block max ----
    float mx = xv[0];
    #pragma unroll
    for (int k = 1; k < 8; ++k) mx = fmaxf(mx, xv[k]);
    #pragma unroll
    for (int off = 16; off > 0; off >>= 1)
        mx = fmaxf(mx, __shfl_xor_sync(0xffffffffu, mx, off));
    if (lane == 0) redf[warp] = mx;
    __syncthreads();
    if (tid == 0) {
        float v = redf[0];
        #pragma unroll
        for (int i = 1; i < 8; ++i) v = fmaxf(v, redf[i]);
        redf[8] = v;
    }
    __syncthreads();
    const float m = redf[8];

    // ---- exp + sum ----
    float s = 0.f;
    #pragma unroll
    for (int k = 0; k < 8; ++k) { xv[k] = expf(xv[k] - m); s += xv[k]; }
    #pragma unroll
    for (int off = 16; off > 0; off >>= 1)
        s += __shfl_xor_sync(0xffffffffu, s, off);
    if (lane == 0) redf[warp] = s;
    __syncthreads();
    if (tid == 0) {
        float v = 0.f;
        #pragma unroll
        for (int i = 0; i < 8; ++i) v += redf[i];
        redf[8] = v;
    }
    __syncthreads();
    const float S = redf[8];

    // ---- normalize (ftz: subnormal affinity -> 0, XLA tie semantics) ----
    int cnt = 0;
    #pragma unroll
    for (int k = 0; k < 8; ++k) {
        float a = xv[k] / S;
        if (a < FLT_MIN_NORMAL) a = 0.f;
        xv[k] = a;
        cnt += (a != 0.f);
    }

    // ---- exclusive scan of nonzero counts (token order) ----
    int incl = cnt;
    #pragma unroll
    for (int off = 1; off < 32; off <<= 1) {
        int v = __shfl_up_sync(0xffffffffu, incl, off);
        if (lane >= off) incl += v;
    }
    int excl = incl - cnt;
    if (lane == 31) wcnt[warp] = incl;
    __syncthreads();
    if (tid == 0) {
        int acc = 0;
        #pragma unroll
        for (int i = 0; i < 8; ++i) { wbase[i] = acc; acc += wcnt[i]; }
        mPtr[0] = acc;
    }
    __syncthreads();
    const int mNZ = mPtr[0];
    const int nzbase = wbase[warp] + excl;

    if (mNZ <= C_) {
        // ---- ordered walk: compact nonzero keys; write zero-token slots ----
        int nzc = nzbase;
        #pragma unroll
        for (int k = 0; k < 8; ++k) {
            int token = 8 * tid + k;
            float a = xv[k];
            if (a != 0.f) {
                sk[nzc] = ((unsigned long long)__float_as_uint(a) << 32)
                        | (unsigned long long)(2047 - token);
                nzc++;
            } else {
                int zr = token - nzc;          // zeros before this token
                tabrow[token] = (zr < C_ - mNZ)
                    ? (unsigned long long)(unsigned)(mNZ + zr)   // val=0
                    : 0xFFFFFFFFull;                             // not chosen
            }
        }
        __syncthreads();

        // ---- rank-by-counting (unique keys; order == jax top_k) ----
        if (tid < mNZ) {
            unsigned long long K = sk[tid];
            int rank = 0;
            for (int j = 0; j < mNZ; ++j) rank += (sk[j] > K);
            int n = 2047 - (int)(K & 0x7FFu);
            tabrow[n] = (K & 0xFFFFFFFF00000000ull) | (unsigned)rank;
        }
    } else {
        // ---- fallback (m > 256): brute-force ranks over all tokens ----
        #pragma unroll
        for (int k = 0; k < 8; ++k) af[8 * tid + k] = xv[k];
        __syncthreads();
        #pragma unroll
        for (int k = 0; k < 8; ++k) {
            int token = 8 * tid + k;
            float ai = xv[k];
            int rank = 0;
            for (int j = 0; j < N_; ++j) {
                float aj = af[j];
                rank += (aj > ai) || (aj == ai && j < token);
            }
            tabrow[token] = (rank < C_)
                ? (((unsigned long long)__float_as_uint(ai) << 32) | (unsigned)rank)
                : 0xFFFFFFFFull;
        }
    }

    // ---- last topk block resets the counter for the next (graph) launch ----
    __syncthreads();
    if (tid == 0) {
        int d = atomicAdd(&g_reset_cnt, 1);
        if (d == NTOPK - 1) {
            g_log_done = 0;
            g_reset_cnt = 0;
        }
    }
}

// ---------------------------------------------------------------------------
// Kernel 2: table-driven writer. Each warp owns whole 256-float output rows
// (row R = consecutive 1KB chunk; R < 131072 -> dispatch, else combine).
// Lane 0 loads the row's 8-byte table entry (slot, valbits), broadcasts it;
// each lane streams two float4s that are zero except component slot-4*c4
// (1.0 for dispatch, value for combine). Single pass at the fill roofline;
// NO ordering dependency, no scatter kernel.
// ---------------------------------------------------------------------------
__global__ __launch_bounds__(256, 4) void writer_kernel(
        float* __restrict__ out, long long out_n) {
    const int tid = threadIdx.x;
    const int lane = tid & 31;
    const long long rows = out_n >> 8;                    // 256 floats per row
    const long long W = ((long long)blockIdx.x * 256 + tid) >> 5;
    const long long wstride = (long long)NWRITE * 8;      // total warps
    float4* o4 = reinterpret_cast<float4*>(out);

    for (long long R = W; R < rows; R += wstride) {
        // decode row -> (tensor, b, n, e); rows are consecutive 256-float chunks
        long long jj = (R >= 131072) ? (R - 131072) : R;  // within-tensor row
        int tensor = (R >= 131072);
        int e = (int)(jj & 15);
        int n = (int)((jj >> 4) & 2047);
        int b = (int)(jj >> 15);

        unsigned long long tab = 0;
        if (lane == 0) tab = g_tab[((long long)(b * 16 + e) << 11) + n];
        tab = __shfl_sync(0xffffffffu, tab, 0);
        int   slot = (int)(unsigned)(tab & 0xFFFFFFFFull);
        float val  = tensor ? __uint_as_float((unsigned)(tab >> 32)) : 1.0f;

        long long base = R << 6;                          // float4 index
        #pragma unroll
        for (int it = 0; it < 2; ++it) {
            int c4 = lane + 32 * it;
            float4 v = make_float4(0.f, 0.f, 0.f, 0.f);
            int r = slot - 4 * c4;
            if (r == 0) v.x = val;
            else if (r == 1) v.y = val;
            else if (r == 2) v.z = val;
            else if (r == 3) v.w = val;
            __stcs(&o4[base + c4], v);
        }
    }

    // tail elements beyond full rows (the two scalar zeros)
    if (blockIdx.x == 0) {
        long long tail = rows << 8;
        if (tid < out_n - tail) out[tail + tid] = 0.f;
    }
}

// ---------------------------------------------------------------------------
extern "C" void kernel_launch(void* const* d_in, const int* in_sizes, int n_in,
                              void* d_out, int out_size) {
    const float* key = nullptr; const float* query = nullptr; const float* temp = nullptr;
    for (int i = 0; i < n_in; ++i) {
        if (in_sizes[i] == B_ * N_ * D_)      key   = (const float*)d_in[i];
        else if (in_sizes[i] == E_ * D_)      query = (const float*)d_in[i];
        else if (in_sizes[i] == 1)            temp  = (const float*)d_in[i];
    }
    if (!key)   key   = (const float*)d_in[0];
    if (!query) query = (const float*)d_in[1];
    if (!temp)  temp  = (const float*)d_in[2];
    float* out = (float*)d_out;

    // K1: logits + topk -> 1MB slot/value table (no output traffic).
    logits_topk_kernel<<<NK1, 256>>>(key, query, temp);
    // K2: single-pass table-driven output writer at the store roofline.
    writer_kernel<<<NWRITE, 256>>>(out, (long long)out_size);
}